// round 2
// baseline (speedup 1.0000x reference)
#include <cuda_runtime.h>
#include <cstdint>

// Farthest point sampling, NPOINT=2.
// Input: xyz [1, B=32, 3, N] float32 (planar: x-plane, y-plane, z-plane per batch).
// Output (float32, [B,2]): idx0 = argmax over y-plane; idx1 = argmax of squared
// distance to point idx0 (first-index tiebreak, matching jnp.argmax).

#define FPS_B 32

// Per-batch best keys: (ordered_float(val) << 32) | ~index.
// max over keys == (max val, min index among equal vals).
__device__ unsigned long long g_best1[FPS_B];
__device__ unsigned long long g_best2[FPS_B];

static __device__ __forceinline__ unsigned long long make_key(float v, unsigned idx) {
    unsigned u = __float_as_uint(v);
    u = (u & 0x80000000u) ? ~u : (u | 0x80000000u);   // order-preserving float->uint
    return ((unsigned long long)u << 32) | (unsigned)(~idx);
}

static __device__ __forceinline__ unsigned long long umax64(unsigned long long a,
                                                            unsigned long long b) {
    return a > b ? a : b;
}

static __device__ __forceinline__ unsigned long long block_reduce_max(unsigned long long v) {
    __shared__ unsigned long long s[8];
    int lane = threadIdx.x & 31;
    int wid  = threadIdx.x >> 5;
    #pragma unroll
    for (int o = 16; o; o >>= 1)
        v = umax64(v, __shfl_down_sync(0xffffffffu, v, o));
    if (lane == 0) s[wid] = v;
    __syncthreads();
    if (wid == 0) {
        v = (lane < (int)(blockDim.x >> 5)) ? s[lane] : 0ull;
        #pragma unroll
        for (int o = 16; o; o >>= 1)
            v = umax64(v, __shfl_down_sync(0xffffffffu, v, o));
    }
    return v;
}

__global__ void fps_init() {
    int i = threadIdx.x;
    if (i < FPS_B) { g_best1[i] = 0ull; g_best2[i] = 0ull; }
}

// Pass 1: per-batch argmax over the y-plane (channel 1).
__global__ void fps_pass1(const float* __restrict__ xyz, int N) {
    const int b = blockIdx.y;
    const float* yp = xyz + (size_t)b * 3 * N + (size_t)N;  // channel 1
    const int N4 = N >> 2;
    const float4* y4 = (const float4*)yp;

    unsigned long long best = 0ull;
    for (int i = blockIdx.x * blockDim.x + threadIdx.x; i < N4;
         i += gridDim.x * blockDim.x) {
        float4 v = y4[i];
        unsigned base = (unsigned)(i << 2);
        best = umax64(best, make_key(v.x, base + 0));
        best = umax64(best, make_key(v.y, base + 1));
        best = umax64(best, make_key(v.z, base + 2));
        best = umax64(best, make_key(v.w, base + 3));
    }
    // scalar tail (N not multiple of 4)
    if (blockIdx.x == 0) {
        for (int i = (N4 << 2) + threadIdx.x; i < N; i += blockDim.x)
            best = umax64(best, make_key(yp[i], (unsigned)i));
    }

    best = block_reduce_max(best);
    if (threadIdx.x == 0) atomicMax(&g_best1[b], best);
}

// Pass 2: per-batch argmax of min(1e10, ||p - centroid0||^2).
__global__ void fps_pass2(const float* __restrict__ xyz, int N) {
    const int b = blockIdx.y;
    const float* xp = xyz + (size_t)b * 3 * N;
    const float* yp = xp + (size_t)N;
    const float* zp = xp + (size_t)2 * N;

    // centroid index from pass 1 (broadcast L2 hit)
    unsigned idx0 = ~(unsigned)(g_best1[b]);
    float cx = __ldg(xp + idx0);
    float cy = __ldg(yp + idx0);
    float cz = __ldg(zp + idx0);

    const int N4 = N >> 2;
    const float4* x4 = (const float4*)xp;
    const float4* y4 = (const float4*)yp;
    const float4* z4 = (const float4*)zp;

    unsigned long long best = 0ull;
    for (int i = blockIdx.x * blockDim.x + threadIdx.x; i < N4;
         i += gridDim.x * blockDim.x) {
        float4 vx = x4[i];
        float4 vy = y4[i];
        float4 vz = z4[i];
        unsigned base = (unsigned)(i << 2);
        {
            float dx = vx.x - cx, dy = vy.x - cy, dz = vz.x - cz;
            float d = fminf(dx * dx + dy * dy + dz * dz, 1e10f);
            best = umax64(best, make_key(d, base + 0));
        }
        {
            float dx = vx.y - cx, dy = vy.y - cy, dz = vz.y - cz;
            float d = fminf(dx * dx + dy * dy + dz * dz, 1e10f);
            best = umax64(best, make_key(d, base + 1));
        }
        {
            float dx = vx.z - cx, dy = vy.z - cy, dz = vz.z - cz;
            float d = fminf(dx * dx + dy * dy + dz * dz, 1e10f);
            best = umax64(best, make_key(d, base + 2));
        }
        {
            float dx = vx.w - cx, dy = vy.w - cy, dz = vz.w - cz;
            float d = fminf(dx * dx + dy * dy + dz * dz, 1e10f);
            best = umax64(best, make_key(d, base + 3));
        }
    }
    if (blockIdx.x == 0) {
        for (int i = (N4 << 2) + threadIdx.x; i < N; i += blockDim.x) {
            float dx = xp[i] - cx, dy = yp[i] - cy, dz = zp[i] - cz;
            float d = fminf(dx * dx + dy * dy + dz * dz, 1e10f);
            best = umax64(best, make_key(d, (unsigned)i));
        }
    }

    best = block_reduce_max(best);
    if (threadIdx.x == 0) atomicMax(&g_best2[b], best);
}

// Output dtype is float32: indices <= 2^24 are exactly representable.
__global__ void fps_finalize(float* __restrict__ out) {
    int b = threadIdx.x;
    if (b < FPS_B) {
        out[2 * b + 0] = (float)(~(unsigned)(g_best1[b]));
        out[2 * b + 1] = (float)(~(unsigned)(g_best2[b]));
    }
}

extern "C" void kernel_launch(void* const* d_in, const int* in_sizes, int n_in,
                              void* d_out, int out_size) {
    const float* xyz = (const float*)d_in[0];
    const int N = in_sizes[0] / (FPS_B * 3);   // [1, 32, 3, N]
    float* out = (float*)d_out;

    const int THREADS = 256;
    const int BLOCKS_PER_BATCH = 160;  // 32*160 = 5120 blocks, full-chip

    fps_init<<<1, FPS_B>>>();
    fps_pass1<<<dim3(BLOCKS_PER_BATCH, FPS_B), THREADS>>>(xyz, N);
    fps_pass2<<<dim3(BLOCKS_PER_BATCH, FPS_B), THREADS>>>(xyz, N);
    fps_finalize<<<1, FPS_B>>>(out);
}

// round 3
// speedup vs baseline: 1.0004x; 1.0004x over previous
#include <cuda_runtime.h>
#include <cstdint>

// Farthest point sampling, NPOINT=2.
// Input: xyz [1, B=32, 3, N] float32 (planar: x-plane, y-plane, z-plane per batch).
// Output (float32, [B,2]): idx0 = argmax over y-plane; idx1 = argmax of squared
// distance to point idx0 (first-index tiebreak, matching jnp.argmax).

#define FPS_B 32

// Per-batch best keys: (ordered_float(val) << 32) | ~index.
// max over keys == (max val, min index among equal vals).
__device__ unsigned long long g_best1[FPS_B];
__device__ unsigned long long g_best2[FPS_B];

static __device__ __forceinline__ unsigned long long make_key(float v, unsigned idx) {
    unsigned u = __float_as_uint(v);
    u = (u & 0x80000000u) ? ~u : (u | 0x80000000u);   // order-preserving float->uint
    return ((unsigned long long)u << 32) | (unsigned)(~idx);
}

static __device__ __forceinline__ unsigned long long umax64(unsigned long long a,
                                                            unsigned long long b) {
    return a > b ? a : b;
}

static __device__ __forceinline__ unsigned long long block_reduce_max(unsigned long long v) {
    __shared__ unsigned long long s[8];
    int lane = threadIdx.x & 31;
    int wid  = threadIdx.x >> 5;
    #pragma unroll
    for (int o = 16; o; o >>= 1)
        v = umax64(v, __shfl_down_sync(0xffffffffu, v, o));
    if (lane == 0) s[wid] = v;
    __syncthreads();
    if (wid == 0) {
        v = (lane < (int)(blockDim.x >> 5)) ? s[lane] : 0ull;
        #pragma unroll
        for (int o = 16; o; o >>= 1)
            v = umax64(v, __shfl_down_sync(0xffffffffu, v, o));
    }
    return v;
}

__global__ void fps_init() {
    int i = threadIdx.x;
    if (i < FPS_B) { g_best1[i] = 0ull; g_best2[i] = 0ull; }
}

// Pass 1: per-batch argmax over the y-plane (channel 1).
__global__ void fps_pass1(const float* __restrict__ xyz, int N) {
    const int b = blockIdx.y;
    const float* yp = xyz + (size_t)b * 3 * N + (size_t)N;  // channel 1
    const int N4 = N >> 2;
    const float4* y4 = (const float4*)yp;

    unsigned long long best = 0ull;
    for (int i = blockIdx.x * blockDim.x + threadIdx.x; i < N4;
         i += gridDim.x * blockDim.x) {
        float4 v = y4[i];
        unsigned base = (unsigned)(i << 2);
        best = umax64(best, make_key(v.x, base + 0));
        best = umax64(best, make_key(v.y, base + 1));
        best = umax64(best, make_key(v.z, base + 2));
        best = umax64(best, make_key(v.w, base + 3));
    }
    // scalar tail (N not multiple of 4)
    if (blockIdx.x == 0) {
        for (int i = (N4 << 2) + threadIdx.x; i < N; i += blockDim.x)
            best = umax64(best, make_key(yp[i], (unsigned)i));
    }

    best = block_reduce_max(best);
    if (threadIdx.x == 0) atomicMax(&g_best1[b], best);
}

// Pass 2: per-batch argmax of min(1e10, ||p - centroid0||^2).
__global__ void fps_pass2(const float* __restrict__ xyz, int N) {
    const int b = blockIdx.y;
    const float* xp = xyz + (size_t)b * 3 * N;
    const float* yp = xp + (size_t)N;
    const float* zp = xp + (size_t)2 * N;

    // centroid index from pass 1 (broadcast L2 hit)
    unsigned idx0 = ~(unsigned)(g_best1[b]);
    float cx = __ldg(xp + idx0);
    float cy = __ldg(yp + idx0);
    float cz = __ldg(zp + idx0);

    const int N4 = N >> 2;
    const float4* x4 = (const float4*)xp;
    const float4* y4 = (const float4*)yp;
    const float4* z4 = (const float4*)zp;

    unsigned long long best = 0ull;
    for (int i = blockIdx.x * blockDim.x + threadIdx.x; i < N4;
         i += gridDim.x * blockDim.x) {
        float4 vx = x4[i];
        float4 vy = y4[i];
        float4 vz = z4[i];
        unsigned base = (unsigned)(i << 2);
        {
            float dx = vx.x - cx, dy = vy.x - cy, dz = vz.x - cz;
            float d = fminf(dx * dx + dy * dy + dz * dz, 1e10f);
            best = umax64(best, make_key(d, base + 0));
        }
        {
            float dx = vx.y - cx, dy = vy.y - cy, dz = vz.y - cz;
            float d = fminf(dx * dx + dy * dy + dz * dz, 1e10f);
            best = umax64(best, make_key(d, base + 1));
        }
        {
            float dx = vx.z - cx, dy = vy.z - cy, dz = vz.z - cz;
            float d = fminf(dx * dx + dy * dy + dz * dz, 1e10f);
            best = umax64(best, make_key(d, base + 2));
        }
        {
            float dx = vx.w - cx, dy = vy.w - cy, dz = vz.w - cz;
            float d = fminf(dx * dx + dy * dy + dz * dz, 1e10f);
            best = umax64(best, make_key(d, base + 3));
        }
    }
    if (blockIdx.x == 0) {
        for (int i = (N4 << 2) + threadIdx.x; i < N; i += blockDim.x) {
            float dx = xp[i] - cx, dy = yp[i] - cy, dz = zp[i] - cz;
            float d = fminf(dx * dx + dy * dy + dz * dz, 1e10f);
            best = umax64(best, make_key(d, (unsigned)i));
        }
    }

    best = block_reduce_max(best);
    if (threadIdx.x == 0) atomicMax(&g_best2[b], best);
}

// Output dtype is float32: indices <= 2^24 are exactly representable.
__global__ void fps_finalize(float* __restrict__ out) {
    int b = threadIdx.x;
    if (b < FPS_B) {
        out[2 * b + 0] = (float)(~(unsigned)(g_best1[b]));
        out[2 * b + 1] = (float)(~(unsigned)(g_best2[b]));
    }
}

extern "C" void kernel_launch(void* const* d_in, const int* in_sizes, int n_in,
                              void* d_out, int out_size) {
    const float* xyz = (const float*)d_in[0];
    const int N = in_sizes[0] / (FPS_B * 3);   // [1, 32, 3, N]
    float* out = (float*)d_out;

    const int THREADS = 256;
    const int BLOCKS_PER_BATCH = 160;  // 32*160 = 5120 blocks, full-chip

    fps_init<<<1, FPS_B>>>();
    fps_pass1<<<dim3(BLOCKS_PER_BATCH, FPS_B), THREADS>>>(xyz, N);
    fps_pass2<<<dim3(BLOCKS_PER_BATCH, FPS_B), THREADS>>>(xyz, N);
    fps_finalize<<<1, FPS_B>>>(out);
}

// round 4
// speedup vs baseline: 1.0873x; 1.0869x over previous
#include <cuda_runtime.h>
#include <cstdint>

// Farthest point sampling, NPOINT=2.
// Input: xyz [1, B=32, 3, N] float32 (planar per batch: x-plane, y-plane, z-plane).
// Output (float32, [B,2]): idx0 = argmax over y-plane; idx1 = argmax of squared
// distance to point idx0 (first-index tiebreak, matching jnp.argmax).
//
// 3 launches: pass1 (y argmax -> per-block partials), pass2 (reduce partials to
// centroid, distance argmax in REVERSE sweep order for L2 reuse of the y-plane,
// x/z loaded evict-first), finalize (reduce partials, write float indices).

#define FPS_B 32
#define BPB   37            // blocks per batch: 37*32 = 1184 = one full wave (148 SM x 8 CTA)

__device__ unsigned long long g_part1[FPS_B * BPB];
__device__ unsigned long long g_part2[FPS_B * BPB];

// key = (ordered_float(val) << 32) | ~index : max-key == (max val, min index on tie)
static __device__ __forceinline__ unsigned long long make_key(float v, unsigned idx) {
    unsigned u = __float_as_uint(v);
    u = (u & 0x80000000u) ? ~u : (u | 0x80000000u);
    return ((unsigned long long)u << 32) | (unsigned)(~idx);
}

static __device__ __forceinline__ unsigned long long umax64(unsigned long long a,
                                                            unsigned long long b) {
    return a > b ? a : b;
}

// full block max (result valid in thread 0 of warp 0)
static __device__ __forceinline__ unsigned long long block_reduce_max(unsigned long long v) {
    __shared__ unsigned long long s[8];
    int lane = threadIdx.x & 31;
    int wid  = threadIdx.x >> 5;
    #pragma unroll
    for (int o = 16; o; o >>= 1)
        v = umax64(v, __shfl_down_sync(0xffffffffu, v, o));
    if (lane == 0) s[wid] = v;
    __syncthreads();
    if (wid == 0) {
        v = (lane < (int)(blockDim.x >> 5)) ? s[lane] : 0ull;
        #pragma unroll
        for (int o = 16; o; o >>= 1)
            v = umax64(v, __shfl_down_sync(0xffffffffu, v, o));
    }
    return v;
}

// Pass 1: per-batch argmax over the y-plane (channel 1). Forward sweep (cached loads)
// so the y tail is L2-resident when pass 2's reverse sweep starts.
__global__ void fps_pass1(const float* __restrict__ xyz, int N) {
    const int b = blockIdx.y;
    const float* yp = xyz + (size_t)b * 3 * N + (size_t)N;
    const int N4 = N >> 2;
    const float4* y4 = (const float4*)yp;

    unsigned long long best = 0ull;
    for (int i = blockIdx.x * blockDim.x + threadIdx.x; i < N4;
         i += gridDim.x * blockDim.x) {
        float4 v = y4[i];
        unsigned base = (unsigned)(i << 2);
        best = umax64(best, make_key(v.x, base + 0));
        best = umax64(best, make_key(v.y, base + 1));
        best = umax64(best, make_key(v.z, base + 2));
        best = umax64(best, make_key(v.w, base + 3));
    }
    if (blockIdx.x == 0) {   // scalar tail (N % 4)
        for (int i = (N4 << 2) + threadIdx.x; i < N; i += blockDim.x)
            best = umax64(best, make_key(yp[i], (unsigned)i));
    }

    best = block_reduce_max(best);
    if (threadIdx.x == 0) g_part1[b * BPB + blockIdx.x] = best;
}

// Pass 2: per-batch argmax of min(1e10, ||p - c0||^2).
// Reverse sweep: y tail (hot in L2 from pass 1) is consumed first.
// x,z loaded with evict-first policy so they don't evict y.
__global__ void fps_pass2(const float* __restrict__ xyz, int N) {
    const int b = blockIdx.y;

    // reduce pass-1 partials for this batch -> centroid index
    __shared__ unsigned idx0_sh;
    {
        unsigned long long v = (threadIdx.x < BPB) ? g_part1[b * BPB + threadIdx.x] : 0ull;
        v = block_reduce_max(v);
        if (threadIdx.x == 0) idx0_sh = ~(unsigned)v;
        __syncthreads();
    }
    const unsigned idx0 = idx0_sh;

    const float* xp = xyz + (size_t)b * 3 * N;
    const float* yp = xp + (size_t)N;
    const float* zp = xp + (size_t)2 * N;
    const float cx = __ldg(xp + idx0);
    const float cy = __ldg(yp + idx0);
    const float cz = __ldg(zp + idx0);

    const int N4 = N >> 2;
    const float4* x4 = (const float4*)xp;
    const float4* y4 = (const float4*)yp;
    const float4* z4 = (const float4*)zp;
    const int stride = gridDim.x * blockDim.x;

    unsigned long long best = 0ull;

    // scalar tail first (highest indices)
    if (blockIdx.x == 0) {
        for (int i = (N4 << 2) + threadIdx.x; i < N; i += blockDim.x) {
            float dx = xp[i] - cx, dy = yp[i] - cy, dz = zp[i] - cz;
            float d = fminf(dx * dx + dy * dy + dz * dz, 1e10f);
            best = umax64(best, make_key(d, (unsigned)i));
        }
    }

    for (int j = blockIdx.x * blockDim.x + threadIdx.x; j < N4; j += stride) {
        int i = N4 - 1 - j;                    // reverse: consecutive tids -> contiguous desc addrs
        float4 vx = __ldcs(x4 + i);            // streaming, evict-first
        float4 vy = y4[i];                     // hot from pass 1 -> keep cached
        float4 vz = __ldcs(z4 + i);
        unsigned base = (unsigned)(i << 2);
        {
            float dx = vx.x - cx, dy = vy.x - cy, dz = vz.x - cz;
            float d = fminf(dx * dx + dy * dy + dz * dz, 1e10f);
            best = umax64(best, make_key(d, base + 0));
        }
        {
            float dx = vx.y - cx, dy = vy.y - cy, dz = vz.y - cz;
            float d = fminf(dx * dx + dy * dy + dz * dz, 1e10f);
            best = umax64(best, make_key(d, base + 1));
        }
        {
            float dx = vx.z - cx, dy = vy.z - cy, dz = vz.z - cz;
            float d = fminf(dx * dx + dy * dy + dz * dz, 1e10f);
            best = umax64(best, make_key(d, base + 2));
        }
        {
            float dx = vx.w - cx, dy = vy.w - cy, dz = vz.w - cz;
            float d = fminf(dx * dx + dy * dy + dz * dz, 1e10f);
            best = umax64(best, make_key(d, base + 3));
        }
    }

    best = block_reduce_max(best);
    if (threadIdx.x == 0) g_part2[b * BPB + blockIdx.x] = best;
}

// Finalize: warp w reduces batch w's partials; writes float indices (exact <= 2^24).
__global__ void fps_finalize(float* __restrict__ out) {
    int w = threadIdx.x >> 5;     // batch
    int l = threadIdx.x & 31;

    unsigned long long v1 = 0ull, v2 = 0ull;
    for (int i = l; i < BPB; i += 32) {
        v1 = umax64(v1, g_part1[w * BPB + i]);
        v2 = umax64(v2, g_part2[w * BPB + i]);
    }
    #pragma unroll
    for (int o = 16; o; o >>= 1) {
        v1 = umax64(v1, __shfl_down_sync(0xffffffffu, v1, o));
        v2 = umax64(v2, __shfl_down_sync(0xffffffffu, v2, o));
    }
    if (l == 0) {
        out[2 * w + 0] = (float)(~(unsigned)v1);
        out[2 * w + 1] = (float)(~(unsigned)v2);
    }
}

extern "C" void kernel_launch(void* const* d_in, const int* in_sizes, int n_in,
                              void* d_out, int out_size) {
    const float* xyz = (const float*)d_in[0];
    const int N = in_sizes[0] / (FPS_B * 3);   // [1, 32, 3, N]
    float* out = (float*)d_out;

    const int THREADS = 256;
    fps_pass1<<<dim3(BPB, FPS_B), THREADS>>>(xyz, N);
    fps_pass2<<<dim3(BPB, FPS_B), THREADS>>>(xyz, N);
    fps_finalize<<<1, FPS_B * 32>>>(out);
}

// round 5
// speedup vs baseline: 1.2707x; 1.1687x over previous
#include <cuda_runtime.h>
#include <cstdint>
#include <math_constants.h>

// Farthest point sampling, NPOINT=2.
// Input: xyz [1, B=32, 3, N] float32 (planar per batch: x-plane, y-plane, z-plane).
// Output (float32, [B,2]): idx0 = argmax over y-plane; idx1 = argmax of squared
// distance to point idx0 (first-index tiebreak, matching jnp.argmax).
//
// 2 launches: pass1 (y argmax partials, resets pass2 ticket), pass2 (distance
// argmax partials, reverse sweep for L2 reuse of y; LAST block folds the final
// reduction + output write via threadfence-reduction).

#define FPS_B 32
#define BPB   37            // 37*32 = 1184 blocks = one full wave (148 SM x 8 CTA x 256 thr)

__device__ unsigned long long g_part1[FPS_B * BPB];
__device__ unsigned long long g_part2[FPS_B * BPB];
__device__ unsigned int       g_ticket;

// key = (ordered_float(val) << 32) | ~index : max-key == (max val, min index on tie)
static __device__ __forceinline__ unsigned long long make_key(float v, unsigned idx) {
    unsigned u = __float_as_uint(v);
    u = (u & 0x80000000u) ? ~u : (u | 0x80000000u);
    return ((unsigned long long)u << 32) | (unsigned)(~idx);
}

static __device__ __forceinline__ unsigned long long umax64(unsigned long long a,
                                                            unsigned long long b) {
    return a > b ? a : b;
}

// full block max (result valid in thread 0 of warp 0)
static __device__ __forceinline__ unsigned long long block_reduce_max(unsigned long long v) {
    __shared__ unsigned long long s[8];
    int lane = threadIdx.x & 31;
    int wid  = threadIdx.x >> 5;
    #pragma unroll
    for (int o = 16; o; o >>= 1)
        v = umax64(v, __shfl_down_sync(0xffffffffu, v, o));
    if (lane == 0) s[wid] = v;
    __syncthreads();
    if (wid == 0) {
        v = (lane < (int)(blockDim.x >> 5)) ? s[lane] : 0ull;
        #pragma unroll
        for (int o = 16; o; o >>= 1)
            v = umax64(v, __shfl_down_sync(0xffffffffu, v, o));
    }
    return v;
}

// cheap per-element update, forward order (keeps FIRST index on tie via >)
#define UPD_GT(bv, bi, v, i) do { if ((v) > (bv)) { (bv) = (v); (bi) = (i); } } while (0)
// reverse order (later-seen index is smaller -> prefer on tie via >=)
#define UPD_GE(bv, bi, v, i) do { if ((v) >= (bv)) { (bv) = (v); (bi) = (i); } } while (0)

// Pass 1: per-batch argmax over the y-plane (channel 1). Forward sweep so the
// y tail is L2-resident when pass 2's reverse sweep starts. Unrolled x2.
__global__ void fps_pass1(const float* __restrict__ xyz, int N) {
    if (blockIdx.x == 0 && blockIdx.y == 0 && threadIdx.x == 0) g_ticket = 0;

    const int b = blockIdx.y;
    const float* yp = xyz + (size_t)b * 3 * N + (size_t)N;
    const int N4 = N >> 2;
    const float4* y4 = (const float4*)yp;
    const int S = gridDim.x * blockDim.x;

    float    bv0 = -CUDART_INF_F, bv1 = -CUDART_INF_F;
    unsigned bi0 = 0u,            bi1 = 0u;

    int i = blockIdx.x * blockDim.x + threadIdx.x;
    for (; i + S < N4; i += 2 * S) {
        float4 a = y4[i];
        float4 c = y4[i + S];
        unsigned ba = (unsigned)(i << 2);
        unsigned bc = (unsigned)((i + S) << 2);
        UPD_GT(bv0, bi0, a.x, ba + 0);
        UPD_GT(bv0, bi0, a.y, ba + 1);
        UPD_GT(bv0, bi0, a.z, ba + 2);
        UPD_GT(bv0, bi0, a.w, ba + 3);
        UPD_GT(bv1, bi1, c.x, bc + 0);
        UPD_GT(bv1, bi1, c.y, bc + 1);
        UPD_GT(bv1, bi1, c.z, bc + 2);
        UPD_GT(bv1, bi1, c.w, bc + 3);
    }
    for (; i < N4; i += S) {
        float4 a = y4[i];
        unsigned ba = (unsigned)(i << 2);
        UPD_GT(bv0, bi0, a.x, ba + 0);
        UPD_GT(bv0, bi0, a.y, ba + 1);
        UPD_GT(bv0, bi0, a.z, ba + 2);
        UPD_GT(bv0, bi0, a.w, ba + 3);
    }
    unsigned long long best = umax64(make_key(bv0, bi0), make_key(bv1, bi1));

    if (blockIdx.x == 0) {   // scalar tail (N % 4)
        float bvt = -CUDART_INF_F; unsigned bit_ = 0u;
        for (int t = (N4 << 2) + threadIdx.x; t < N; t += blockDim.x)
            UPD_GT(bvt, bit_, yp[t], (unsigned)t);
        best = umax64(best, make_key(bvt, bit_));
    }

    best = block_reduce_max(best);
    if (threadIdx.x == 0) g_part1[b * BPB + blockIdx.x] = best;
}

// Pass 2: per-batch argmax of min(1e10, ||p - c0||^2), reverse sweep.
// x,z loaded evict-first so they don't evict the hot y tail.
// Last block to finish performs the global reduction and writes the output.
__global__ void fps_pass2(const float* __restrict__ xyz, int N,
                          float* __restrict__ out) {
    const int b = blockIdx.y;

    // reduce pass-1 partials for this batch -> centroid index
    __shared__ unsigned idx0_sh;
    {
        unsigned long long v = (threadIdx.x < BPB) ? g_part1[b * BPB + threadIdx.x] : 0ull;
        v = block_reduce_max(v);
        if (threadIdx.x == 0) idx0_sh = ~(unsigned)v;
        __syncthreads();
    }
    const unsigned idx0 = idx0_sh;

    const float* xp = xyz + (size_t)b * 3 * N;
    const float* yp = xp + (size_t)N;
    const float* zp = xp + (size_t)2 * N;
    const float cx = __ldg(xp + idx0);
    const float cy = __ldg(yp + idx0);
    const float cz = __ldg(zp + idx0);

    const int N4 = N >> 2;
    const float4* x4 = (const float4*)xp;
    const float4* y4 = (const float4*)yp;
    const float4* z4 = (const float4*)zp;
    const int stride = gridDim.x * blockDim.x;

    float    bv = -CUDART_INF_F;
    unsigned bi = 0u;

    // scalar tail first (highest indices), forward order -> '>' keeps first
    if (blockIdx.x == 0) {
        for (int t = (N4 << 2) + threadIdx.x; t < N; t += blockDim.x) {
            float dx = xp[t] - cx, dy = yp[t] - cy, dz = zp[t] - cz;
            float d = fminf(dx * dx + dy * dy + dz * dz, 1e10f);
            UPD_GT(bv, bi, d, (unsigned)t);
        }
    }

    for (int j = blockIdx.x * blockDim.x + threadIdx.x; j < N4; j += stride) {
        int i = N4 - 1 - j;                    // reverse: hot y tail consumed first
        float4 vx = __ldcs(x4 + i);            // streaming, evict-first
        float4 vy = y4[i];                     // hot from pass 1 -> keep cached
        float4 vz = __ldcs(z4 + i);
        unsigned base = (unsigned)(i << 2);
        {
            float dx = vx.x - cx, dy = vy.x - cy, dz = vz.x - cz;
            float d = fminf(dx * dx + dy * dy + dz * dz, 1e10f);
            UPD_GE(bv, bi, d, base + 0);
        }
        {
            float dx = vx.y - cx, dy = vy.y - cy, dz = vz.y - cz;
            float d = fminf(dx * dx + dy * dy + dz * dz, 1e10f);
            UPD_GE(bv, bi, d, base + 1);
        }
        {
            float dx = vx.z - cx, dy = vy.z - cy, dz = vz.z - cz;
            float d = fminf(dx * dx + dy * dy + dz * dz, 1e10f);
            UPD_GE(bv, bi, d, base + 2);
        }
        {
            float dx = vx.w - cx, dy = vy.w - cy, dz = vz.w - cz;
            float d = fminf(dx * dx + dy * dy + dz * dz, 1e10f);
            UPD_GE(bv, bi, d, base + 3);
        }
    }

    unsigned long long best = block_reduce_max(make_key(bv, bi));
    if (threadIdx.x == 0) g_part2[b * BPB + blockIdx.x] = best;

    // ---- folded finalize: last block reduces all partials, writes output ----
    __shared__ bool s_last;
    __threadfence();
    if (threadIdx.x == 0) {
        unsigned t = atomicAdd(&g_ticket, 1u);
        s_last = (t == gridDim.x * gridDim.y - 1);
    }
    __syncthreads();
    if (s_last) {
        // 8 warps; warp w handles batches w, w+8, w+16, w+24
        int wid  = threadIdx.x >> 5;
        int lane = threadIdx.x & 31;
        for (int bb = wid; bb < FPS_B; bb += (int)(blockDim.x >> 5)) {
            unsigned long long v1 = 0ull, v2 = 0ull;
            for (int k = lane; k < BPB; k += 32) {
                v1 = umax64(v1, g_part1[bb * BPB + k]);
                v2 = umax64(v2, g_part2[bb * BPB + k]);
            }
            #pragma unroll
            for (int o = 16; o; o >>= 1) {
                v1 = umax64(v1, __shfl_down_sync(0xffffffffu, v1, o));
                v2 = umax64(v2, __shfl_down_sync(0xffffffffu, v2, o));
            }
            if (lane == 0) {
                out[2 * bb + 0] = (float)(~(unsigned)v1);   // exact: idx <= 2^24
                out[2 * bb + 1] = (float)(~(unsigned)v2);
            }
        }
    }
}

extern "C" void kernel_launch(void* const* d_in, const int* in_sizes, int n_in,
                              void* d_out, int out_size) {
    const float* xyz = (const float*)d_in[0];
    const int N = in_sizes[0] / (FPS_B * 3);   // [1, 32, 3, N]
    float* out = (float*)d_out;

    const int THREADS = 256;
    fps_pass1<<<dim3(BPB, FPS_B), THREADS>>>(xyz, N);
    fps_pass2<<<dim3(BPB, FPS_B), THREADS>>>(xyz, N, out);
}